// round 13
// baseline (speedup 1.0000x reference)
#include <cuda_runtime.h>

typedef unsigned long long ULL;

// ---------------- packed f32x2 helpers (sm_103a FFMA2 path) ----------------
__device__ __forceinline__ ULL pk2(float lo, float hi) {
    ULL r; asm("mov.b64 %0, {%1,%2};" : "=l"(r) : "f"(lo), "f"(hi)); return r;
}
__device__ __forceinline__ void upk2(ULL v, float& lo, float& hi) {
    asm("mov.b64 {%0,%1}, %2;" : "=f"(lo), "=f"(hi) : "l"(v));
}
__device__ __forceinline__ ULL fma2(ULL a, ULL b, ULL c) {
    ULL d; asm("fma.rn.f32x2 %0, %1, %2, %3;" : "=l"(d) : "l"(a), "l"(b), "l"(c)); return d;
}
__device__ __forceinline__ ULL add2(ULL a, ULL b) {
    ULL d; asm("add.rn.f32x2 %0, %1, %2;" : "=l"(d) : "l"(a), "l"(b)); return d;
}
// packed relu: per-half max.f32 (lowers to 2 FMNMX; pack movs elided by ptxas)
__device__ __forceinline__ ULL relu2(ULL a) {
    ULL d;
    asm("{\n\t"
        ".reg .f32 lo, hi;\n\t"
        "mov.b64 {lo, hi}, %1;\n\t"
        "max.f32 lo, lo, 0f00000000;\n\t"
        "max.f32 hi, hi, 0f00000000;\n\t"
        "mov.b64 %0, {lo, hi};\n\t"
        "}" : "=l"(d) : "l"(a));
    return d;
}
__device__ __forceinline__ float rsqrt_approx(float x) {
    float r; asm("rsqrt.approx.f32 %0, %1;" : "=f"(r) : "f"(x)); return r;
}

// ---------------- problem constants ----------------
constexpr int K    = 32;       // experts
constexpr int DI   = 10;       // input size
constexpr int DH   = 20;       // hidden size
constexpr int B    = 262144;
constexpr int THREADS = 128;
constexpr int R    = 4;        // batch rows per thread (2 packed pairs)
constexpr int NP   = R / 2;    // row pairs per thread = 2
constexpr int SPLIT = 4;       // expert splits across gridDim.y
constexpr int KPC  = K / SPLIT;    // experts per CTA = 8
constexpr int GRIDX = B / (R * THREADS);   // 512

// per-split partials: float4 j covers rows 2j,2j+1 as (n0,d0,n1,d1)
__device__ float4 g_part[SPLIT][B / 2];

// shared layout in ULL units (per CTA: 8 experts) — ALL values duplicated (v,v)
constexpr int U_W1 = 0;                      // [kl][h][i] (w,w) : 1600 ULL
constexpr int U_BW = U_W1 + KPC * DH * DI;   // [kl][h]{(b1,b1),(w2,w2)} : 320 ULL
constexpr int U_PV = U_BW + KPC * DH * 2;    // [kl][i] (-2p,-2p) : 80 ULL
constexpr int U_C2 = U_PV + KPC * DI;        // [kl] (|p|^2,|p|^2) : 8 ULL
constexpr int U_B2 = U_C2 + KPC;             // [kl] (b2,b2) : 8 ULL
constexpr int U_END = U_B2 + KPC;            // 2016 ULL
constexpr int SM_FLOATS = U_END * 2;         // 4032 floats = 16.1 KB

__global__ void __launch_bounds__(THREADS)
piecewise_mlp_main(const float* __restrict__ in,
                   const float* __restrict__ W1,
                   const float* __restrict__ b1,
                   const float* __restrict__ W2,
                   const float* __restrict__ b2,
                   const float* __restrict__ proto)
{
    extern __shared__ float sm[];
    ULL* smU = (ULL*)sm;
    const int split = blockIdx.y;
    const int kbase = split * KPC;

    // ---- stage this split's 8 experts (duplicated pairs) ----
    for (int idx = threadIdx.x; idx < KPC * DH * DI; idx += THREADS) {
        int kl = idx / (DH * DI), rem = idx % (DH * DI);
        int h = rem / DI, i = rem % DI;
        float w = W1[((kbase + kl) * DH + h) * DI + i];
        smU[U_W1 + idx] = pk2(w, w);
    }
    for (int idx = threadIdx.x; idx < KPC * DH * 2; idx += THREADS) {
        int kl = idx / (DH * 2), rem = idx % (DH * 2);
        int h = rem / 2, w = rem % 2;
        const float* src = (w == 0) ? b1 : W2;   // W2 is [K,1,DH] flat
        float v = src[(kbase + kl) * DH + h];
        smU[U_BW + idx] = pk2(v, v);
    }
    for (int idx = threadIdx.x; idx < KPC * DI; idx += THREADS) {
        int kl = idx / DI, i = idx % DI;
        float p = -2.0f * proto[(kbase + kl) * DI + i];
        smU[U_PV + idx] = pk2(p, p);
    }
    if (threadIdx.x < KPC) {
        int k = kbase + threadIdx.x;
        float s = 0.0f;
        #pragma unroll
        for (int i = 0; i < DI; i++) {
            float a = proto[k * DI + i];
            s = fmaf(a, a, s);
        }
        smU[U_C2 + threadIdx.x] = pk2(s, s);
        float bb = b2[k];
        smU[U_B2 + threadIdx.x] = pk2(bb, bb);
    }
    __syncthreads();

    // ---- load R=4 batch rows (160B contiguous), build batch-pair packs ----
    // pair p covers rows (4gt+2p, 4gt+2p+1): x2[p][i] = (x_row2p[i], x_row2p+1[i])
    const int gt = blockIdx.x * THREADS + threadIdx.x;
    const float4* q = (const float4*)(in + (size_t)gt * R * DI);
    float a[R * DI];
    #pragma unroll
    for (int v = 0; v < R * DI / 4; v++) {     // 10 float4 loads
        float4 f = q[v];
        a[v * 4 + 0] = f.x; a[v * 4 + 1] = f.y;
        a[v * 4 + 2] = f.z; a[v * 4 + 3] = f.w;
    }
    ULL x2[NP][DI];
    #pragma unroll
    for (int p = 0; p < NP; p++)
        #pragma unroll
        for (int i = 0; i < DI; i++)
            x2[p][i] = pk2(a[(2 * p) * DI + i], a[(2 * p + 1) * DI + i]);

    // |x|^2 packs: (xx_row2p, xx_row2p+1)
    ULL xxp[NP];
    #pragma unroll
    for (int p = 0; p < NP; p++) {
        ULL acc = 0ull;
        #pragma unroll
        for (int i = 0; i < DI; i++) acc = fma2(x2[p][i], x2[p][i], acc);
        xxp[p] = acc;
    }

    ULL num2[NP], den2[NP];
    #pragma unroll
    for (int p = 0; p < NP; p++) { num2[p] = 0ull; den2[p] = 0ull; }

    const ULL* w1p = smU + U_W1;
    const ulonglong2* bwp = (const ulonglong2*)(smU + U_BW);  // [kl*DH+h] = (b1dup, w2dup)
    const ULL* pvp = smU + U_PV;
    const ULL* c2p = smU + U_C2;
    const ULL* b2p = smU + U_B2;

    #pragma unroll 1
    for (int kl = 0; kl < KPC; kl++) {
        // ---- gating: d2 = |p|^2 + |x|^2 + sum_i (-2 p_i) x_i, per row pair ----
        const ulonglong2* pq = (const ulonglong2*)(pvp + kl * DI);
        ulonglong2 p0 = pq[0], p1 = pq[1], p2 = pq[2], p3 = pq[3], p4 = pq[4];
        ULL c2u = c2p[kl];
        ULL e2[NP];
        #pragma unroll
        for (int p = 0; p < NP; p++) {
            ULL d2 = add2(c2u, xxp[p]);
            d2 = fma2(x2[p][0], p0.x, d2);
            d2 = fma2(x2[p][1], p0.y, d2);
            d2 = fma2(x2[p][2], p1.x, d2);
            d2 = fma2(x2[p][3], p1.y, d2);
            d2 = fma2(x2[p][4], p2.x, d2);
            d2 = fma2(x2[p][5], p2.y, d2);
            d2 = fma2(x2[p][6], p3.x, d2);
            d2 = fma2(x2[p][7], p3.y, d2);
            d2 = fma2(x2[p][8], p4.x, d2);
            d2 = fma2(x2[p][9], p4.y, d2);
            float da, db; upk2(d2, da, db);
            da = fmaxf(da, 1e-12f);
            db = fmaxf(db, 1e-12f);
            float ea = __expf(-da * rsqrt_approx(da));
            float eb = __expf(-db * rsqrt_approx(db));
            e2[p] = pk2(ea, eb);
            den2[p] = add2(den2[p], e2[p]);
        }

        // ---- expert MLP: pred pack per row pair ----
        ULL b2u = b2p[kl];                     // (b2, b2)
        ULL pred2[NP];
        #pragma unroll
        for (int p = 0; p < NP; p++) pred2[p] = b2u;

        #pragma unroll
        for (int h = 0; h < DH; h++) {
            const ulonglong2* wrow = (const ulonglong2*)(w1p + (kl * DH + h) * DI);
            ulonglong2 w0 = wrow[0], w1v = wrow[1], w2v = wrow[2], w3 = wrow[3], w4 = wrow[4];
            ulonglong2 bwv = bwp[kl * DH + h];  // (b1 dup, w2 dup)
            #pragma unroll
            for (int p = 0; p < NP; p++) {
                ULL acc = bwv.x;
                acc = fma2(x2[p][0], w0.x,  acc);
                acc = fma2(x2[p][1], w0.y,  acc);
                acc = fma2(x2[p][2], w1v.x, acc);
                acc = fma2(x2[p][3], w1v.y, acc);
                acc = fma2(x2[p][4], w2v.x, acc);
                acc = fma2(x2[p][5], w2v.y, acc);
                acc = fma2(x2[p][6], w3.x,  acc);
                acc = fma2(x2[p][7], w3.y,  acc);
                acc = fma2(x2[p][8], w4.x,  acc);
                acc = fma2(x2[p][9], w4.y,  acc);
                // packed relu then packed w2 accumulate (both rows at once)
                pred2[p] = fma2(relu2(acc), bwv.y, pred2[p]);
            }
        }

        // ---- packed num accumulation: (pred_r0, pred_r1) * (e_r0, e_r1) ----
        #pragma unroll
        for (int p = 0; p < NP; p++)
            num2[p] = fma2(pred2[p], e2[p], num2[p]);
    }

    // ---- write partial (num, den) per row for this split ----
    float4* dst = &g_part[split][(size_t)gt * 2];
    #pragma unroll
    for (int p = 0; p < NP; p++) {
        float n0, n1, d0, d1;
        upk2(num2[p], n0, n1);
        upk2(den2[p], d0, d1);
        dst[p] = make_float4(n0, d0, n1, d1);
    }
}

// ---- combine: out[row] = sum_s num / sum_s den ; 1 row per thread ----
constexpr int CTHREADS = 256;
constexpr int CGRID = B / CTHREADS;   // 1024

__global__ void __launch_bounds__(CTHREADS)
piecewise_mlp_combine(float* __restrict__ out)
{
    const int t = blockIdx.x * CTHREADS + threadIdx.x;   // row index
    float n = 0.0f, d = 0.0f;
    #pragma unroll
    for (int s = 0; s < SPLIT; s++) {
        float2 v = ((const float2*)g_part[s])[t];        // coalesced 8B
        n += v.x;
        d += v.y;
    }
    out[t] = __fdividef(n, d);
}

extern "C" void kernel_launch(void* const* d_in, const int* in_sizes, int n_in,
                              void* d_out, int out_size)
{
    const float* in    = (const float*)d_in[0];
    const float* W1    = (const float*)d_in[1];
    const float* b1    = (const float*)d_in[2];
    const float* W2    = (const float*)d_in[3];
    const float* b2    = (const float*)d_in[4];
    const float* proto = (const float*)d_in[5];
    float* out = (float*)d_out;

    dim3 grid(GRIDX, SPLIT);
    piecewise_mlp_main<<<grid, THREADS, SM_FLOATS * sizeof(float)>>>(
        in, W1, b1, W2, b2, proto);
    piecewise_mlp_combine<<<CGRID, CTHREADS>>>(out);
}

// round 14
// speedup vs baseline: 1.2039x; 1.2039x over previous
#include <cuda_runtime.h>

typedef unsigned long long ULL;

// ---------------- packed f32x2 helpers (sm_103a FFMA2 path) ----------------
__device__ __forceinline__ ULL pk2(float lo, float hi) {
    ULL r; asm("mov.b64 %0, {%1,%2};" : "=l"(r) : "f"(lo), "f"(hi)); return r;
}
__device__ __forceinline__ void upk2(ULL v, float& lo, float& hi) {
    asm("mov.b64 {%0,%1}, %2;" : "=f"(lo), "=f"(hi) : "l"(v));
}
__device__ __forceinline__ ULL fma2(ULL a, ULL b, ULL c) {
    ULL d; asm("fma.rn.f32x2 %0, %1, %2, %3;" : "=l"(d) : "l"(a), "l"(b), "l"(c)); return d;
}
__device__ __forceinline__ ULL add2(ULL a, ULL b) {
    ULL d; asm("add.rn.f32x2 %0, %1, %2;" : "=l"(d) : "l"(a), "l"(b)); return d;
}
__device__ __forceinline__ float rsqrt_approx(float x) {
    float r; asm("rsqrt.approx.f32 %0, %1;" : "=f"(r) : "f"(x)); return r;
}

// ---------------- problem constants ----------------
constexpr int K    = 32;       // experts
constexpr int DI   = 10;       // input size
constexpr int DH   = 20;       // hidden size
constexpr int NHP  = DH / 2;   // hidden pairs = 10
constexpr int B    = 262144;
constexpr int THREADS = 128;
constexpr int R    = 4;        // batch rows per thread
constexpr int SPLIT = 4;       // expert splits across gridDim.y
constexpr int KPC  = K / SPLIT;    // experts per CTA = 8
constexpr int NKPC = KPC / 2;      // expert pairs per CTA = 4
constexpr int GRIDX = B / (R * THREADS);   // 512

// per-split partials: float4 j covers rows 2j,2j+1 as (n0,d0,n1,d1)
__device__ float4 g_part[SPLIT][B / 2];

// shared layout in ULL units (per CTA: 8 experts)
constexpr int U_W1 = 0;                       // [kl][hp][i] (h,h+1) pairs : 800 ULL
constexpr int U_BW = U_W1 + KPC * NHP * DI;   // [kl][hp]{(b1,b1'),(w2,w2')} : 160 ULL
constexpr int U_PV = U_BW + KPC * NHP * 2;    // [kpl][i] (-2p_k, -2p_k') : 40 ULL
constexpr int U_C2 = U_PV + NKPC * DI;        // [kpl] (|p_k|^2, |p_k'|^2) : 4 ULL
constexpr int U_B2 = U_C2 + NKPC;             // [kl] (b2, 0) : 8 ULL
constexpr int U_END = U_B2 + KPC;             // 1012 ULL
constexpr int SM_FLOATS = U_END * 2;          // ~8.1 KB

__global__ void __launch_bounds__(THREADS)
piecewise_mlp_main(const float* __restrict__ in,
                   const float* __restrict__ W1,
                   const float* __restrict__ b1,
                   const float* __restrict__ W2,
                   const float* __restrict__ b2,
                   const float* __restrict__ proto)
{
    extern __shared__ float sm[];
    ULL* smU = (ULL*)sm;
    const int split = blockIdx.y;
    const int kbase = split * KPC;

    // ---- stage this split's 8 experts ----
    for (int idx = threadIdx.x; idx < KPC * NHP * DI; idx += THREADS) {
        int kl = idx / (NHP * DI), rem = idx % (NHP * DI);
        int hp = rem / DI, i = rem % DI;
        int k = kbase + kl;
        smU[U_W1 + idx] = pk2(W1[(k * DH + 2 * hp) * DI + i],
                              W1[(k * DH + 2 * hp + 1) * DI + i]);
    }
    for (int idx = threadIdx.x; idx < KPC * NHP * 2; idx += THREADS) {
        int kl = idx / (NHP * 2), rem = idx % (NHP * 2);
        int hp = rem / 2, w = rem % 2;
        int k = kbase + kl;
        const float* src = (w == 0) ? b1 : W2;   // W2 is [K,1,DH] flat
        smU[U_BW + idx] = pk2(src[k * DH + 2 * hp], src[k * DH + 2 * hp + 1]);
    }
    for (int idx = threadIdx.x; idx < NKPC * DI; idx += THREADS) {
        int kpl = idx / DI, i = idx % DI;
        int k = kbase + 2 * kpl;
        smU[U_PV + idx] = pk2(-2.0f * proto[k * DI + i],
                              -2.0f * proto[(k + 1) * DI + i]);
    }
    if (threadIdx.x < NKPC) {
        int k = kbase + 2 * threadIdx.x;
        float s0 = 0.0f, s1 = 0.0f;
        #pragma unroll
        for (int i = 0; i < DI; i++) {
            float a = proto[k * DI + i];
            float c = proto[(k + 1) * DI + i];
            s0 = fmaf(a, a, s0);
            s1 = fmaf(c, c, s1);
        }
        smU[U_C2 + threadIdx.x] = pk2(s0, s1);
    }
    if (threadIdx.x < KPC)
        smU[U_B2 + threadIdx.x] = pk2(b2[kbase + threadIdx.x], 0.0f);
    __syncthreads();

    // ---- load R=4 batch rows (160B contiguous), build dup packs (x,x) ----
    const int gt = blockIdx.x * THREADS + threadIdx.x;
    const float4* q = (const float4*)(in + (size_t)gt * R * DI);
    ULL x2[R][DI];
    #pragma unroll
    for (int v = 0; v < R * DI / 4; v++) {     // 10 float4 loads
        float4 f = q[v];
        int b0 = v * 4;
        x2[(b0 + 0) / DI][(b0 + 0) % DI] = pk2(f.x, f.x);
        x2[(b0 + 1) / DI][(b0 + 1) % DI] = pk2(f.y, f.y);
        x2[(b0 + 2) / DI][(b0 + 2) % DI] = pk2(f.z, f.z);
        x2[(b0 + 3) / DI][(b0 + 3) % DI] = pk2(f.w, f.w);
    }

    // |x|^2 as dup packs, once per row
    ULL xxp[R];
    #pragma unroll
    for (int r = 0; r < R; r++) {
        ULL acc = 0ull;
        #pragma unroll
        for (int i = 0; i < DI; i++) acc = fma2(x2[r][i], x2[r][i], acc);
        xxp[r] = acc;
    }

    ULL num2[R], den2[R];
    #pragma unroll
    for (int r = 0; r < R; r++) { num2[r] = 0ull; den2[r] = 0ull; }

    const ULL* w1p = smU + U_W1;
    const ULL* bwp = smU + U_BW;
    const ULL* pvp = smU + U_PV;
    const ULL* c2p = smU + U_C2;
    const ULL* b2p = smU + U_B2;

    // unroll 2: expose two expert-pair iterations so ptxas can hoist the next
    // iteration's LDS into the current iteration's fma2 shadow
    #pragma unroll 2
    for (int kp = 0; kp < NKPC; kp++) {
        // ---- gating: d2 = |p|^2 + |x|^2 + sum_i (-2 p_i) x_i, packed per expert pair ----
        const ulonglong2* pq = (const ulonglong2*)(pvp + kp * DI);
        ulonglong2 p0 = pq[0], p1 = pq[1], p2 = pq[2], p3 = pq[3], p4 = pq[4];
        ULL c2u = c2p[kp];
        ULL e2[R];
        #pragma unroll
        for (int r = 0; r < R; r++) {
            ULL d2 = add2(c2u, xxp[r]);
            d2 = fma2(x2[r][0], p0.x, d2);
            d2 = fma2(x2[r][1], p0.y, d2);
            d2 = fma2(x2[r][2], p1.x, d2);
            d2 = fma2(x2[r][3], p1.y, d2);
            d2 = fma2(x2[r][4], p2.x, d2);
            d2 = fma2(x2[r][5], p2.y, d2);
            d2 = fma2(x2[r][6], p3.x, d2);
            d2 = fma2(x2[r][7], p3.y, d2);
            d2 = fma2(x2[r][8], p4.x, d2);
            d2 = fma2(x2[r][9], p4.y, d2);
            float da, db; upk2(d2, da, db);
            da = fmaxf(da, 1e-12f);
            db = fmaxf(db, 1e-12f);
            float ea = __expf(-da * rsqrt_approx(da));
            float eb = __expf(-db * rsqrt_approx(db));
            e2[r] = pk2(ea, eb);
            den2[r] = add2(den2[r], e2[r]);
        }

        // ---- MLPs for the two experts of this pair ----
        float predk[2][R];
        #pragma unroll
        for (int sub = 0; sub < 2; sub++) {
            int kl = 2 * kp + sub;
            ULL b2u = b2p[kl];                 // (b2, 0)
            ULL pred2[R];
            #pragma unroll
            for (int r = 0; r < R; r++) pred2[r] = b2u;

            #pragma unroll
            for (int hp = 0; hp < NHP; hp++) {
                const ulonglong2* wrow = (const ulonglong2*)(w1p + (kl * NHP + hp) * DI);
                ulonglong2 w0 = wrow[0], w1v = wrow[1], w2v = wrow[2], w3 = wrow[3], w4 = wrow[4];
                ulonglong2 bwv = ((const ulonglong2*)bwp)[kl * NHP + hp]; // (b1pair, w2pair)
                #pragma unroll
                for (int r = 0; r < R; r++) {
                    ULL acc = bwv.x;
                    acc = fma2(x2[r][0], w0.x,  acc);
                    acc = fma2(x2[r][1], w0.y,  acc);
                    acc = fma2(x2[r][2], w1v.x, acc);
                    acc = fma2(x2[r][3], w1v.y, acc);
                    acc = fma2(x2[r][4], w2v.x, acc);
                    acc = fma2(x2[r][5], w2v.y, acc);
                    acc = fma2(x2[r][6], w3.x,  acc);
                    acc = fma2(x2[r][7], w3.y,  acc);
                    acc = fma2(x2[r][8], w4.x,  acc);
                    acc = fma2(x2[r][9], w4.y,  acc);
                    float hl, hh; upk2(acc, hl, hh);
                    hl = fmaxf(hl, 0.0f);
                    hh = fmaxf(hh, 0.0f);
                    pred2[r] = fma2(pk2(hl, hh), bwv.y, pred2[r]);
                }
            }
            #pragma unroll
            for (int r = 0; r < R; r++) {
                float pl, ph; upk2(pred2[r], pl, ph);
                predk[sub][r] = pl + ph;       // b2 folded into init
            }
        }

        // ---- packed num accumulation: (pred_k, pred_k+1) * (e_k, e_k+1) ----
        #pragma unroll
        for (int r = 0; r < R; r++)
            num2[r] = fma2(pk2(predk[0][r], predk[1][r]), e2[r], num2[r]);
    }

    // ---- write partial (num, den) per row for this split ----
    float n[R], d[R];
    #pragma unroll
    for (int r = 0; r < R; r++) {
        float nl, nh, dl, dh;
        upk2(num2[r], nl, nh); upk2(den2[r], dl, dh);
        n[r] = nl + nh;
        d[r] = dl + dh;
    }
    float4* dst = &g_part[split][(size_t)gt * 2];
    dst[0] = make_float4(n[0], d[0], n[1], d[1]);
    dst[1] = make_float4(n[2], d[2], n[3], d[3]);
}

// ---- combine: out[row] = sum_s num / sum_s den ; 1 row per thread ----
constexpr int CTHREADS = 256;
constexpr int CGRID = B / CTHREADS;   // 1024

__global__ void __launch_bounds__(CTHREADS)
piecewise_mlp_combine(float* __restrict__ out)
{
    const int t = blockIdx.x * CTHREADS + threadIdx.x;   // row index
    float n = 0.0f, d = 0.0f;
    #pragma unroll
    for (int s = 0; s < SPLIT; s++) {
        float2 v = ((const float2*)g_part[s])[t];        // coalesced 8B
        n += v.x;
        d += v.y;
    }
    out[t] = __fdividef(n, d);
}

extern "C" void kernel_launch(void* const* d_in, const int* in_sizes, int n_in,
                              void* d_out, int out_size)
{
    const float* in    = (const float*)d_in[0];
    const float* W1    = (const float*)d_in[1];
    const float* b1    = (const float*)d_in[2];
    const float* W2    = (const float*)d_in[3];
    const float* b2    = (const float*)d_in[4];
    const float* proto = (const float*)d_in[5];
    float* out = (float*)d_out;

    dim3 grid(GRIDX, SPLIT);
    piecewise_mlp_main<<<grid, THREADS, SM_FLOATS * sizeof(float)>>>(
        in, W1, b1, W2, b2, proto);
    piecewise_mlp_combine<<<CGRID, CTHREADS>>>(out);
}

// round 15
// speedup vs baseline: 1.2349x; 1.0257x over previous
#include <cuda_runtime.h>

typedef unsigned long long ULL;

// ---------------- packed f32x2 helpers (sm_103a FFMA2 path) ----------------
__device__ __forceinline__ ULL pk2(float lo, float hi) {
    ULL r; asm("mov.b64 %0, {%1,%2};" : "=l"(r) : "f"(lo), "f"(hi)); return r;
}
__device__ __forceinline__ void upk2(ULL v, float& lo, float& hi) {
    asm("mov.b64 {%0,%1}, %2;" : "=f"(lo), "=f"(hi) : "l"(v));
}
__device__ __forceinline__ ULL fma2(ULL a, ULL b, ULL c) {
    ULL d; asm("fma.rn.f32x2 %0, %1, %2, %3;" : "=l"(d) : "l"(a), "l"(b), "l"(c)); return d;
}
__device__ __forceinline__ ULL add2(ULL a, ULL b) {
    ULL d; asm("add.rn.f32x2 %0, %1, %2;" : "=l"(d) : "l"(a), "l"(b)); return d;
}
__device__ __forceinline__ float rsqrt_approx(float x) {
    float r; asm("rsqrt.approx.f32 %0, %1;" : "=f"(r) : "f"(x)); return r;
}

// ---------------- problem constants ----------------
constexpr int K    = 32;       // experts
constexpr int DI   = 10;       // input size
constexpr int DH   = 20;       // hidden size
constexpr int NHP  = DH / 2;   // hidden pairs = 10
constexpr int B    = 262144;
constexpr int THREADS = 128;
constexpr int R    = 4;        // batch rows per thread
constexpr int SPLIT = 4;       // expert splits across gridDim.y
constexpr int KPC  = K / SPLIT;    // experts per CTA = 8
constexpr int NKPC = KPC / 2;      // expert pairs per CTA = 4
constexpr int GRIDX = B / (R * THREADS);   // 512

// per-split partials: float4 j covers rows 2j,2j+1 as (n0,d0,n1,d1)
__device__ float4 g_part[SPLIT][B / 2];

// shared layout in ULL units (per CTA: 8 experts)
constexpr int U_W1 = 0;                       // [kl][hp][i] (h,h+1) pairs : 800 ULL
constexpr int U_BW = U_W1 + KPC * NHP * DI;   // [kl][hp]{(b1,b1'),(w2,w2')} : 160 ULL
constexpr int U_PV = U_BW + KPC * NHP * 2;    // [kpl][i] (-2p_k, -2p_k') : 40 ULL
constexpr int U_C2 = U_PV + NKPC * DI;        // [kpl] (|p_k|^2, |p_k'|^2) : 4 ULL
constexpr int U_B2 = U_C2 + NKPC;             // [kl] (b2, 0) : 8 ULL
constexpr int U_END = U_B2 + KPC;             // 1012 ULL
constexpr int SM_FLOATS = U_END * 2;          // ~8.1 KB

__global__ void __launch_bounds__(THREADS)
piecewise_mlp_main(const float* __restrict__ in,
                   const float* __restrict__ W1,
                   const float* __restrict__ b1,
                   const float* __restrict__ W2,
                   const float* __restrict__ b2,
                   const float* __restrict__ proto)
{
    extern __shared__ float sm[];
    ULL* smU = (ULL*)sm;
    const int split = blockIdx.y;
    const int kbase = split * KPC;

    // ---- stage this split's 8 experts ----
    for (int idx = threadIdx.x; idx < KPC * NHP * DI; idx += THREADS) {
        int kl = idx / (NHP * DI), rem = idx % (NHP * DI);
        int hp = rem / DI, i = rem % DI;
        int k = kbase + kl;
        smU[U_W1 + idx] = pk2(W1[(k * DH + 2 * hp) * DI + i],
                              W1[(k * DH + 2 * hp + 1) * DI + i]);
    }
    for (int idx = threadIdx.x; idx < KPC * NHP * 2; idx += THREADS) {
        int kl = idx / (NHP * 2), rem = idx % (NHP * 2);
        int hp = rem / 2, w = rem % 2;
        int k = kbase + kl;
        const float* src = (w == 0) ? b1 : W2;   // W2 is [K,1,DH] flat
        smU[U_BW + idx] = pk2(src[k * DH + 2 * hp], src[k * DH + 2 * hp + 1]);
    }
    for (int idx = threadIdx.x; idx < NKPC * DI; idx += THREADS) {
        int kpl = idx / DI, i = idx % DI;
        int k = kbase + 2 * kpl;
        smU[U_PV + idx] = pk2(-2.0f * proto[k * DI + i],
                              -2.0f * proto[(k + 1) * DI + i]);
    }
    if (threadIdx.x < NKPC) {
        int k = kbase + 2 * threadIdx.x;
        float s0 = 0.0f, s1 = 0.0f;
        #pragma unroll
        for (int i = 0; i < DI; i++) {
            float a = proto[k * DI + i];
            float c = proto[(k + 1) * DI + i];
            s0 = fmaf(a, a, s0);
            s1 = fmaf(c, c, s1);
        }
        smU[U_C2 + threadIdx.x] = pk2(s0, s1);
    }
    if (threadIdx.x < KPC)
        smU[U_B2 + threadIdx.x] = pk2(b2[kbase + threadIdx.x], 0.0f);
    __syncthreads();

    // ---- load R=4 batch rows (160B contiguous), build dup packs (x,x) ----
    const int gt = blockIdx.x * THREADS + threadIdx.x;
    const float4* q = (const float4*)(in + (size_t)gt * R * DI);
    ULL x2[R][DI];
    #pragma unroll
    for (int v = 0; v < R * DI / 4; v++) {     // 10 float4 loads
        float4 f = q[v];
        int b0 = v * 4;
        x2[(b0 + 0) / DI][(b0 + 0) % DI] = pk2(f.x, f.x);
        x2[(b0 + 1) / DI][(b0 + 1) % DI] = pk2(f.y, f.y);
        x2[(b0 + 2) / DI][(b0 + 2) % DI] = pk2(f.z, f.z);
        x2[(b0 + 3) / DI][(b0 + 3) % DI] = pk2(f.w, f.w);
    }

    // |x|^2 as dup packs, once per row
    ULL xxp[R];
    #pragma unroll
    for (int r = 0; r < R; r++) {
        ULL acc = 0ull;
        #pragma unroll
        for (int i = 0; i < DI; i++) acc = fma2(x2[r][i], x2[r][i], acc);
        xxp[r] = acc;
    }

    ULL num2[R], den2[R];
    #pragma unroll
    for (int r = 0; r < R; r++) { num2[r] = 0ull; den2[r] = 0ull; }

    const ULL* w1p = smU + U_W1;
    const ULL* bwp = smU + U_BW;
    const ULL* pvp = smU + U_PV;
    const ULL* c2p = smU + U_C2;
    const ULL* b2p = smU + U_B2;

    #pragma unroll 1
    for (int kp = 0; kp < NKPC; kp++) {
        // ---- gating: d2 = |p|^2 + |x|^2 + sum_i (-2 p_i) x_i, packed per expert pair ----
        const ulonglong2* pq = (const ulonglong2*)(pvp + kp * DI);
        ulonglong2 p0 = pq[0], p1 = pq[1], p2 = pq[2], p3 = pq[3], p4 = pq[4];
        ULL c2u = c2p[kp];
        ULL e2[R];
        #pragma unroll
        for (int r = 0; r < R; r++) {
            ULL d2 = add2(c2u, xxp[r]);
            d2 = fma2(x2[r][0], p0.x, d2);
            d2 = fma2(x2[r][1], p0.y, d2);
            d2 = fma2(x2[r][2], p1.x, d2);
            d2 = fma2(x2[r][3], p1.y, d2);
            d2 = fma2(x2[r][4], p2.x, d2);
            d2 = fma2(x2[r][5], p2.y, d2);
            d2 = fma2(x2[r][6], p3.x, d2);
            d2 = fma2(x2[r][7], p3.y, d2);
            d2 = fma2(x2[r][8], p4.x, d2);
            d2 = fma2(x2[r][9], p4.y, d2);
            float da, db; upk2(d2, da, db);
            da = fmaxf(da, 1e-12f);
            db = fmaxf(db, 1e-12f);
            float ea = __expf(-da * rsqrt_approx(da));
            float eb = __expf(-db * rsqrt_approx(db));
            e2[r] = pk2(ea, eb);
            den2[r] = add2(den2[r], e2[r]);
        }

        // ---- MLPs for the two experts of this pair ----
        float predk[2][R];
        #pragma unroll
        for (int sub = 0; sub < 2; sub++) {
            int kl = 2 * kp + sub;
            ULL b2u = b2p[kl];                 // (b2, 0)
            ULL pred2[R];
            #pragma unroll
            for (int r = 0; r < R; r++) pred2[r] = b2u;

            #pragma unroll
            for (int hp = 0; hp < NHP; hp++) {
                const ulonglong2* wrow = (const ulonglong2*)(w1p + (kl * NHP + hp) * DI);
                ulonglong2 w0 = wrow[0], w1v = wrow[1], w2v = wrow[2], w3 = wrow[3], w4 = wrow[4];
                ulonglong2 bwv = ((const ulonglong2*)bwp)[kl * NHP + hp]; // (b1pair, w2pair)
                #pragma unroll
                for (int r = 0; r < R; r++) {
                    ULL acc = bwv.x;
                    acc = fma2(x2[r][0], w0.x,  acc);
                    acc = fma2(x2[r][1], w0.y,  acc);
                    acc = fma2(x2[r][2], w1v.x, acc);
                    acc = fma2(x2[r][3], w1v.y, acc);
                    acc = fma2(x2[r][4], w2v.x, acc);
                    acc = fma2(x2[r][5], w2v.y, acc);
                    acc = fma2(x2[r][6], w3.x,  acc);
                    acc = fma2(x2[r][7], w3.y,  acc);
                    acc = fma2(x2[r][8], w4.x,  acc);
                    acc = fma2(x2[r][9], w4.y,  acc);
                    float hl, hh; upk2(acc, hl, hh);
                    hl = fmaxf(hl, 0.0f);
                    hh = fmaxf(hh, 0.0f);
                    pred2[r] = fma2(pk2(hl, hh), bwv.y, pred2[r]);
                }
            }
            #pragma unroll
            for (int r = 0; r < R; r++) {
                float pl, ph; upk2(pred2[r], pl, ph);
                predk[sub][r] = pl + ph;       // b2 folded into init
            }
        }

        // ---- packed num accumulation: (pred_k, pred_k+1) * (e_k, e_k+1) ----
        #pragma unroll
        for (int r = 0; r < R; r++)
            num2[r] = fma2(pk2(predk[0][r], predk[1][r]), e2[r], num2[r]);
    }

    // ---- write partial (num, den) per row for this split ----
    float n[R], d[R];
    #pragma unroll
    for (int r = 0; r < R; r++) {
        float nl, nh, dl, dh;
        upk2(num2[r], nl, nh); upk2(den2[r], dl, dh);
        n[r] = nl + nh;
        d[r] = dl + dh;
    }
    float4* dst = &g_part[split][(size_t)gt * 2];
    dst[0] = make_float4(n[0], d[0], n[1], d[1]);
    dst[1] = make_float4(n[2], d[2], n[3], d[3]);
}

// ---- combine: 2 rows per thread via float4 loads (8 independent LDGs) ----
constexpr int CTHREADS = 256;
constexpr int CGRID = B / (2 * CTHREADS);   // 512

__global__ void __launch_bounds__(CTHREADS)
piecewise_mlp_combine(float* __restrict__ out)
{
    const int t = blockIdx.x * CTHREADS + threadIdx.x;   // 2-row group index
    float n0 = 0.0f, d0 = 0.0f, n1 = 0.0f, d1 = 0.0f;
    #pragma unroll
    for (int s = 0; s < SPLIT; s++) {
        float4 v = g_part[s][t];             // (n0,d0,n1,d1) for rows 2t,2t+1
        n0 += v.x; d0 += v.y;
        n1 += v.z; d1 += v.w;
    }
    float2 o;
    o.x = __fdividef(n0, d0);
    o.y = __fdividef(n1, d1);
    ((float2*)out)[t] = o;
}

extern "C" void kernel_launch(void* const* d_in, const int* in_sizes, int n_in,
                              void* d_out, int out_size)
{
    const float* in    = (const float*)d_in[0];
    const float* W1    = (const float*)d_in[1];
    const float* b1    = (const float*)d_in[2];
    const float* W2    = (const float*)d_in[3];
    const float* b2    = (const float*)d_in[4];
    const float* proto = (const float*)d_in[5];
    float* out = (float*)d_out;

    dim3 grid(GRIDX, SPLIT);
    piecewise_mlp_main<<<grid, THREADS, SM_FLOATS * sizeof(float)>>>(
        in, W1, b1, W2, b2, proto);
    piecewise_mlp_combine<<<CGRID, CTHREADS>>>(out);
}